// round 12
// baseline (speedup 1.0000x reference)
#include <cuda_runtime.h>
#include <cuda_bf16.h>
#include <math.h>
#include <stdint.h>

// ---------------- problem constants ----------------
#define LSEQ   4096
#define WIN    5
#define NC     4086
#define NCPAD  4096
#define VOCAB  32000
#define DIM    128
#define MT     32              // m-tiles (128 centers each)
#define NSEG   9               // n-segments (7x28 + 2x27 = 250 tiles)
#define NUNITS (MT * NSEG)     // 288 CTAs (one wave at 2 CTAs/SM)
#define LOG2E  1.4426950408889634f

// ---------------- device scratch ----------------
__device__ __nv_bfloat16  d_ctxh[NCPAD * DIM];   // bf16(ctx * log2e)
__device__ __nv_bfloat16  d_Wh[VOCAB * DIM];     // bf16(W)
__device__ float          d_tgtlogit[NCPAD];
__device__ float          d_partialU[NUNITS * 128];
__device__ float          d_blocksum[32];
__device__ unsigned       d_arrive;              // zero-init; self-resetting

// ---------------- asm helpers ----------------
__device__ __forceinline__ uint32_t smem_to_u32(const void* p) {
    uint32_t a;
    asm("{ .reg .u64 t; cvta.to.shared.u64 t, %1; cvt.u32.u64 %0, t; }" : "=r"(a) : "l"(p));
    return a;
}
#define CP_ASYNC16(dst, src) \
    asm volatile("cp.async.cg.shared.global [%0], [%1], 16;" :: "r"(dst), "l"(src))
#define CP_COMMIT() asm volatile("cp.async.commit_group;" ::: "memory")
#define CP_WAIT1()  asm volatile("cp.async.wait_group 1;" ::: "memory")

__device__ __forceinline__ void ldsm_x4(uint32_t& r0, uint32_t& r1, uint32_t& r2,
                                        uint32_t& r3, uint32_t addr) {
    asm volatile("ldmatrix.sync.aligned.m8n8.x4.shared.b16 {%0,%1,%2,%3}, [%4];"
                 : "=r"(r0), "=r"(r1), "=r"(r2), "=r"(r3) : "r"(addr));
}
__device__ __forceinline__ void mma_bf16(float* c, const uint32_t* a, const uint32_t* b) {
    asm volatile("mma.sync.aligned.m16n8k16.row.col.f32.bf16.bf16.f32 "
                 "{%0,%1,%2,%3}, {%4,%5,%6,%7}, {%8,%9}, {%0,%1,%2,%3};"
                 : "+f"(c[0]), "+f"(c[1]), "+f"(c[2]), "+f"(c[3])
                 : "r"(a[0]), "r"(a[1]), "r"(a[2]), "r"(a[3]), "r"(b[0]), "r"(b[1]));
}
__device__ __forceinline__ float ex2(float x) {
    float y;
    asm("ex2.approx.f32 %0, %1;" : "=f"(y) : "f"(x));
    return y;
}
// exp2 entirely on FMA+ALU pipes: magic-number rounding, no FRND/F2I/MUFU.
__device__ __forceinline__ float exp2m(float x) {
    const float MAGIC = 12582912.0f;            // 1.5 * 2^23
    float t = x + MAGIC;                        // rint(x) in low mantissa bits
    float n = t - MAGIC;                        // = rint(x)
    float f = x - n;                            // f in [-0.5, 0.5]
    float p = fmaf(f, 1.33988744e-3f, 9.61843736e-3f);
    p = fmaf(f, p, 5.55017485e-2f);
    p = fmaf(f, p, 2.40226479e-1f);
    p = fmaf(f, p, 6.93147203e-1f);
    p = fmaf(f, p, 1.0f);
    float s = __int_as_float((__float_as_int(t) + 127) << 23);  // 2^rint(x)
    return p * s;
}

// ---------------- prep kernel ----------------
// blocks [0,NCPAD): ctx + target logit (self-converting tokens)
// blocks [NCPAD,..): W -> bf16
__global__ void prep_kernel(const void* __restrict__ toks,
                            const float* __restrict__ emb,
                            const float* __restrict__ Wm) {
    if (blockIdx.x < NCPAD) {
        __shared__ int   s_is64;
        __shared__ int   stok[11];
        __shared__ float sred[4];
        int c = blockIdx.x, d = threadIdx.x;
        const int* p32 = (const int*)toks;
        if (d == 0) {
            int any = 0;
#pragma unroll
            for (int i = 0; i < 16; ++i) any |= p32[2 * i + 1];
            s_is64 = (any == 0);
        }
        __syncthreads();
        if (d < 11 && c < NC)
            stok[d] = s_is64 ? (int)(((const long long*)toks)[c + d]) : p32[c + d];
        __syncthreads();
        float s = 0.f;
        if (c < NC) {
#pragma unroll
            for (int j = 0; j < 11; ++j) {
                if (j == WIN) continue;
                s += emb[(size_t)stok[j] * DIM + d];
            }
            s *= (1.0f / (2 * WIN));
        }
        d_ctxh[c * DIM + d] = __float2bfloat16(s * LOG2E);
        if (c < NC) {
            float pr = s * Wm[(size_t)stok[WIN] * DIM + d];
#pragma unroll
            for (int o = 16; o; o >>= 1) pr += __shfl_xor_sync(0xffffffffu, pr, o);
            if ((d & 31) == 0) sred[d >> 5] = pr;
            __syncthreads();
            if (d == 0) d_tgtlogit[c] = sred[0] + sred[1] + sred[2] + sred[3];
        }
    } else {
        int i = (blockIdx.x - NCPAD) * 128 + threadIdx.x;  // uint4 index
        if (i >= VOCAB * DIM / 8) return;
        float4 w0 = ((const float4*)Wm)[2 * i];
        float4 w1 = ((const float4*)Wm)[2 * i + 1];
        uint4 v;
        v.x = ((uint32_t)__bfloat16_as_ushort(__float2bfloat16(w0.y)) << 16) | __bfloat16_as_ushort(__float2bfloat16(w0.x));
        v.y = ((uint32_t)__bfloat16_as_ushort(__float2bfloat16(w0.w)) << 16) | __bfloat16_as_ushort(__float2bfloat16(w0.z));
        v.z = ((uint32_t)__bfloat16_as_ushort(__float2bfloat16(w1.y)) << 16) | __bfloat16_as_ushort(__float2bfloat16(w1.x));
        v.w = ((uint32_t)__bfloat16_as_ushort(__float2bfloat16(w1.w)) << 16) | __bfloat16_as_ushort(__float2bfloat16(w1.z));
        ((uint4*)d_Wh)[i] = v;
    }
}

// ---------------- main fused GEMM + sum-exp ----------------
// 2 CTAs/SM: smem per CTA = A 32KB + 2-stage B 64KB = 96KB; regs <= 128.
#define SMEM_A_OFF 0
#define SMEM_B_OFF 32768
#define SMEM_MAIN  (32768 + 2 * 32768)

__global__ void __launch_bounds__(256, 2) gemm_sumexp_kernel() {
    extern __shared__ char smem[];
    uint32_t sb = smem_to_u32(smem);
    const int tid  = threadIdx.x;
    const int lane = tid & 31;
    const int wid  = tid >> 5;
    const int warp_m = wid & 3;
    const int warp_n = wid >> 2;
    const int mtile = blockIdx.x;
    const int seg   = blockIdx.y;
    const int nbase = (seg < 7) ? seg * 28 : 196 + (seg - 7) * 27;
    const int len   = (seg < 7) ? 28 : 27;

    const uint32_t sA = sb + SMEM_A_OFF;
    const uint32_t sB = sb + SMEM_B_OFF;

    // ---- async-load A tile (128x128 bf16, swizzled) ----
    {
        const char* src = (const char*)(d_ctxh + (size_t)mtile * 128 * DIM);
#pragma unroll
        for (int i = 0; i < 8; ++i) {
            int j = tid + i * 256;
            int row = j >> 4, cb = j & 15;
            CP_ASYNC16(sA + row * 256 + ((cb ^ (row & 7)) << 4),
                       src + row * 256 + cb * 16);
        }
    }
    auto loadB = [&](int t) {
        const char* src = (const char*)(d_Wh + (size_t)(nbase + t) * 128 * DIM);
        uint32_t dstb = sB + (t & 1) * 32768;
#pragma unroll
        for (int i = 0; i < 8; ++i) {
            int j = tid + i * 256;
            int row = j >> 4, cb = j & 15;
            CP_ASYNC16(dstb + row * 256 + ((cb ^ (row & 7)) << 4),
                       src + row * 256 + cb * 16);
        }
    };
    loadB(0); CP_COMMIT();   // group: A + B0
    loadB(1); CP_COMMIT();

    // B ldsm addressing: row&7 == lane&7 for all chunks
    const uint32_t rowbase = (uint32_t)(warp_n * 64 + (lane & 7)) * 256;
    uint32_t colsw[4];
#pragma unroll
    for (int kk = 0; kk < 4; ++kk)
        colsw[kk] = (uint32_t)(((kk * 4 + (lane >> 3)) ^ (lane & 7)) << 4);

    uint32_t Afrag[2][8][4];          // persistent A fragments (64 regs)
    float    su[2][2] = {{0.f, 0.f}, {0.f, 0.f}};

    for (int t = 0; t < len; ++t) {
        CP_WAIT1();
        __syncthreads();
        if (t == 0) {
#pragma unroll
            for (int ms = 0; ms < 2; ++ms)
#pragma unroll
                for (int ks = 0; ks < 8; ++ks) {
                    int row = warp_m * 32 + ms * 16 + (lane & 7) + 8 * ((lane >> 3) & 1);
                    int cb  = ks * 2 + (lane >> 4);
                    uint32_t addr = sA + row * 256 + ((cb ^ (row & 7)) << 4);
                    ldsm_x4(Afrag[ms][ks][0], Afrag[ms][ks][1],
                            Afrag[ms][ks][2], Afrag[ms][ks][3], addr);
                }
        }
        const uint32_t tbase = sB + (t & 1) * 32768 + rowbase;

        // 8 n8-chunks; epilogue split across pipes: C0 -> MUFU ex2,
        // C1 -> FMA/ALU-pipe exp2m (no cvt, no MUFU)
#pragma unroll
        for (int j8 = 0; j8 < 8; ++j8) {
            uint32_t Bf[8][2];
            const uint32_t jbase = tbase + (uint32_t)(j8 * 8 * 256);
#pragma unroll
            for (int kk = 0; kk < 4; ++kk)
                ldsm_x4(Bf[2 * kk][0], Bf[2 * kk][1],
                        Bf[2 * kk + 1][0], Bf[2 * kk + 1][1],
                        jbase + colsw[kk]);
            float C0[4] = {0.f, 0.f, 0.f, 0.f};
            float C1[4] = {0.f, 0.f, 0.f, 0.f};
#pragma unroll
            for (int ks = 0; ks < 8; ++ks) {
                mma_bf16(C0, Afrag[0][ks], Bf[ks]);
                mma_bf16(C1, Afrag[1][ks], Bf[ks]);
            }
            su[0][0] += ex2(C0[0]) + ex2(C0[1]);
            su[0][1] += ex2(C0[2]) + ex2(C0[3]);
            su[1][0] += exp2m(C1[0]) + exp2m(C1[1]);
            su[1][1] += exp2m(C1[2]) + exp2m(C1[3]);
        }
        __syncthreads();
        if (t + 2 < len) { loadB(t + 2); CP_COMMIT(); }
    }

    // ---- deterministic reduction ----
#pragma unroll
    for (int ms = 0; ms < 2; ++ms)
#pragma unroll
        for (int h = 0; h < 2; ++h) {
            float x = su[ms][h];
            x += __shfl_xor_sync(0xffffffffu, x, 1);
            x += __shfl_xor_sync(0xffffffffu, x, 2);
            su[ms][h] = x;
        }
    __syncthreads();
    float* sred = (float*)smem;
    if ((lane & 3) == 0) {
#pragma unroll
        for (int ms = 0; ms < 2; ++ms)
#pragma unroll
            for (int h = 0; h < 2; ++h) {
                int srow = warp_m * 32 + ms * 16 + h * 8 + (lane >> 2);
                sred[warp_n * 128 + srow] = su[ms][h];
            }
    }
    __syncthreads();
    if (tid < 128) {
        int u = mtile * NSEG + seg;
        d_partialU[u * 128 + tid] = sred[tid] + sred[128 + tid];
    }
}

// ---------------- loss: single launch, last-block finishes ----------------
__global__ void loss_kernel(float* __restrict__ out) {
    __shared__ float sred[4];
    __shared__ int   slast;
    int m = blockIdx.x, r = threadIdx.x;
    int c = m * 128 + r;
    float s = 0.f;
    if (c < NC) {
        float t = 0.f;
#pragma unroll
        for (int g = 0; g < NSEG; ++g) t += d_partialU[(m * NSEG + g) * 128 + r];
        s = __logf(t) - d_tgtlogit[c];
    }
#pragma unroll
    for (int o = 16; o; o >>= 1) s += __shfl_xor_sync(0xffffffffu, s, o);
    if ((r & 31) == 0) sred[r >> 5] = s;
    __syncthreads();
    if (r == 0) {
        d_blocksum[m] = sred[0] + sred[1] + sred[2] + sred[3];
        __threadfence();
        slast = (atomicAdd(&d_arrive, 1u) == 31u);
    }
    __syncthreads();
    if (slast && r == 0) {
        float tot = 0.f;
#pragma unroll
        for (int i = 0; i < 32; ++i) tot += __ldcg(&d_blocksum[i]);
        out[0] = tot;
        d_arrive = 0u;
    }
}

// ---------------- launch ----------------
extern "C" void kernel_launch(void* const* d_in, const int* in_sizes, int n_in,
                              void* d_out, int out_size) {
    const void*  toks = d_in[0];
    const float* emb  = (const float*)d_in[1];
    const float* Wm   = (const float*)d_in[2];
    float* out = (float*)d_out;

    cudaFuncSetAttribute(gemm_sumexp_kernel,
                         cudaFuncAttributeMaxDynamicSharedMemorySize, SMEM_MAIN);

    prep_kernel<<<NCPAD + (VOCAB * DIM / 8 + 127) / 128, 128>>>(toks, emb, Wm);
    gemm_sumexp_kernel<<<dim3(MT, NSEG), 256, SMEM_MAIN>>>();
    loss_kernel<<<32, 128>>>(out);
}

// round 13
// speedup vs baseline: 1.7585x; 1.7585x over previous
#include <cuda_runtime.h>
#include <cuda_bf16.h>
#include <math.h>
#include <stdint.h>

// ---------------- problem constants ----------------
#define LSEQ   4096
#define WIN    5
#define NC     4086
#define NCPAD  4096
#define VOCAB  32000
#define DIM    128
#define MT     32              // m-tiles (128 centers each)
#define NSEG   9               // n-segments (7x28 + 2x27 = 250 tiles)
#define NUNITS (MT * NSEG)     // 288 worker CTAs (+1 watcher)
#define LOG2E  1.4426950408889634f

// ---------------- device scratch ----------------
__device__ __nv_bfloat16  d_ctxh[NCPAD * DIM];   // bf16(ctx * log2e)
__device__ __nv_bfloat16  d_Wh[VOCAB * DIM];     // bf16(W)
__device__ float          d_tgtlogit[NCPAD];
__device__ float          d_partialU[NUNITS * 128];
__device__ unsigned       d_arrive;              // zero-init; self-resetting

// ---------------- asm helpers ----------------
__device__ __forceinline__ uint32_t smem_to_u32(const void* p) {
    uint32_t a;
    asm("{ .reg .u64 t; cvta.to.shared.u64 t, %1; cvt.u32.u64 %0, t; }" : "=r"(a) : "l"(p));
    return a;
}
#define CP_ASYNC16(dst, src) \
    asm volatile("cp.async.cg.shared.global [%0], [%1], 16;" :: "r"(dst), "l"(src))
#define CP_COMMIT() asm volatile("cp.async.commit_group;" ::: "memory")
#define CP_WAIT1()  asm volatile("cp.async.wait_group 1;" ::: "memory")

__device__ __forceinline__ void ldsm_x4(uint32_t& r0, uint32_t& r1, uint32_t& r2,
                                        uint32_t& r3, uint32_t addr) {
    asm volatile("ldmatrix.sync.aligned.m8n8.x4.shared.b16 {%0,%1,%2,%3}, [%4];"
                 : "=r"(r0), "=r"(r1), "=r"(r2), "=r"(r3) : "r"(addr));
}
__device__ __forceinline__ void mma_bf16(float* c, const uint32_t* a, const uint32_t* b) {
    asm volatile("mma.sync.aligned.m16n8k16.row.col.f32.bf16.bf16.f32 "
                 "{%0,%1,%2,%3}, {%4,%5,%6,%7}, {%8,%9}, {%0,%1,%2,%3};"
                 : "+f"(c[0]), "+f"(c[1]), "+f"(c[2]), "+f"(c[3])
                 : "r"(a[0]), "r"(a[1]), "r"(a[2]), "r"(a[3]), "r"(b[0]), "r"(b[1]));
}
__device__ __forceinline__ float ex2(float x) {
    float y;
    asm("ex2.approx.f32 %0, %1;" : "=f"(y) : "f"(x));
    return y;
}

// ---------------- prep kernel ----------------
// blocks [0,NCPAD): ctx + target logit (self-converting tokens)
// blocks [NCPAD,..): W -> bf16
__global__ void prep_kernel(const void* __restrict__ toks,
                            const float* __restrict__ emb,
                            const float* __restrict__ Wm) {
    if (blockIdx.x < NCPAD) {
        __shared__ int   s_is64;
        __shared__ int   stok[11];
        __shared__ float sred[4];
        int c = blockIdx.x, d = threadIdx.x;
        const int* p32 = (const int*)toks;
        if (d == 0) {
            int any = 0;
#pragma unroll
            for (int i = 0; i < 16; ++i) any |= p32[2 * i + 1];
            s_is64 = (any == 0);
        }
        __syncthreads();
        if (d < 11 && c < NC)
            stok[d] = s_is64 ? (int)(((const long long*)toks)[c + d]) : p32[c + d];
        __syncthreads();
        float s = 0.f;
        if (c < NC) {
#pragma unroll
            for (int j = 0; j < 11; ++j) {
                if (j == WIN) continue;
                s += emb[(size_t)stok[j] * DIM + d];
            }
            s *= (1.0f / (2 * WIN));
        }
        d_ctxh[c * DIM + d] = __float2bfloat16(s * LOG2E);
        if (c < NC) {
            float pr = s * Wm[(size_t)stok[WIN] * DIM + d];
#pragma unroll
            for (int o = 16; o; o >>= 1) pr += __shfl_xor_sync(0xffffffffu, pr, o);
            if ((d & 31) == 0) sred[d >> 5] = pr;
            __syncthreads();
            if (d == 0) d_tgtlogit[c] = sred[0] + sred[1] + sred[2] + sred[3];
        }
    } else {
        int i = (blockIdx.x - NCPAD) * 128 + threadIdx.x;  // uint4 index
        if (i >= VOCAB * DIM / 8) return;
        float4 w0 = ((const float4*)Wm)[2 * i];
        float4 w1 = ((const float4*)Wm)[2 * i + 1];
        uint4 v;
        v.x = ((uint32_t)__bfloat16_as_ushort(__float2bfloat16(w0.y)) << 16) | __bfloat16_as_ushort(__float2bfloat16(w0.x));
        v.y = ((uint32_t)__bfloat16_as_ushort(__float2bfloat16(w0.w)) << 16) | __bfloat16_as_ushort(__float2bfloat16(w0.z));
        v.z = ((uint32_t)__bfloat16_as_ushort(__float2bfloat16(w1.y)) << 16) | __bfloat16_as_ushort(__float2bfloat16(w1.x));
        v.w = ((uint32_t)__bfloat16_as_ushort(__float2bfloat16(w1.w)) << 16) | __bfloat16_as_ushort(__float2bfloat16(w1.z));
        ((uint4*)d_Wh)[i] = v;
    }
}

// ---------------- main fused GEMM + sum-exp + watcher loss ----------------
// 2 CTAs/SM: smem per CTA = A 32KB + 2-stage B 64KB = 96KB; regs <= 128.
// grid = NUNITS + 1; last CTA is the loss watcher (separate low-reg branch).
#define SMEM_A_OFF 0
#define SMEM_B_OFF 32768
#define SMEM_MAIN  (32768 + 2 * 32768)

__global__ void __launch_bounds__(256, 2) gemm_sumexp_kernel(float* __restrict__ out) {
    extern __shared__ char smem[];
    const int bid = blockIdx.x;
    const int tid = threadIdx.x;

    if (bid == NUNITS) {
        // ---------- watcher CTA: wait for all workers, reduce loss ----------
        float* lred = (float*)smem;
        if (tid == 0) {
            while (atomicAdd(&d_arrive, 0u) != NUNITS) __nanosleep(200);
        }
        __syncthreads();
        __threadfence();
        float s = 0.f;
#pragma unroll
        for (int i = 0; i < 16; ++i) {
            int c = tid + i * 256;
            if (c < NC) {
                int m = c >> 7, r = c & 127;
                float t = 0.f;
#pragma unroll
                for (int g = 0; g < NSEG; ++g)
                    t += __ldcg(&d_partialU[(m * NSEG + g) * 128 + r]);
                s += __logf(t) - d_tgtlogit[c];
            }
        }
        lred[tid] = s;
        __syncthreads();
#pragma unroll
        for (int o = 128; o; o >>= 1) {
            if (tid < o) lred[tid] += lred[tid + o];
            __syncthreads();
        }
        if (tid == 0) { out[0] = lred[0]; d_arrive = 0u; }
        return;
    }

    // ---------- worker CTA (exact R11 body) ----------
    uint32_t sb = smem_to_u32(smem);
    const int lane = tid & 31;
    const int wid  = tid >> 5;
    const int warp_m = wid & 3;
    const int warp_n = wid >> 2;
    const int mtile = bid / NSEG;
    const int seg   = bid - mtile * NSEG;
    const int nbase = (seg < 7) ? seg * 28 : 196 + (seg - 7) * 27;
    const int len   = (seg < 7) ? 28 : 27;

    const uint32_t sA = sb + SMEM_A_OFF;
    const uint32_t sB = sb + SMEM_B_OFF;

    // ---- async-load A tile (128x128 bf16, swizzled) ----
    {
        const char* src = (const char*)(d_ctxh + (size_t)mtile * 128 * DIM);
#pragma unroll
        for (int i = 0; i < 8; ++i) {
            int j = tid + i * 256;
            int row = j >> 4, cb = j & 15;
            CP_ASYNC16(sA + row * 256 + ((cb ^ (row & 7)) << 4),
                       src + row * 256 + cb * 16);
        }
    }
    auto loadB = [&](int t) {
        const char* src = (const char*)(d_Wh + (size_t)(nbase + t) * 128 * DIM);
        uint32_t dstb = sB + (t & 1) * 32768;
#pragma unroll
        for (int i = 0; i < 8; ++i) {
            int j = tid + i * 256;
            int row = j >> 4, cb = j & 15;
            CP_ASYNC16(dstb + row * 256 + ((cb ^ (row & 7)) << 4),
                       src + row * 256 + cb * 16);
        }
    };
    loadB(0); CP_COMMIT();   // group: A + B0
    loadB(1); CP_COMMIT();

    // B ldsm addressing: row&7 == lane&7 for all chunks
    const uint32_t rowbase = (uint32_t)(warp_n * 64 + (lane & 7)) * 256;
    uint32_t colsw[4];
#pragma unroll
    for (int kk = 0; kk < 4; ++kk)
        colsw[kk] = (uint32_t)(((kk * 4 + (lane >> 3)) ^ (lane & 7)) << 4);

    uint32_t Afrag[2][8][4];          // persistent A fragments (64 regs)
    float    su[2][2] = {{0.f, 0.f}, {0.f, 0.f}};

    for (int t = 0; t < len; ++t) {
        CP_WAIT1();
        __syncthreads();
        if (t == 0) {
#pragma unroll
            for (int ms = 0; ms < 2; ++ms)
#pragma unroll
                for (int ks = 0; ks < 8; ++ks) {
                    int row = warp_m * 32 + ms * 16 + (lane & 7) + 8 * ((lane >> 3) & 1);
                    int cb  = ks * 2 + (lane >> 4);
                    uint32_t addr = sA + row * 256 + ((cb ^ (row & 7)) << 4);
                    ldsm_x4(Afrag[ms][ks][0], Afrag[ms][ks][1],
                            Afrag[ms][ks][2], Afrag[ms][ks][3], addr);
                }
        }
        const uint32_t tbase = sB + (t & 1) * 32768 + rowbase;

        // 8 n8-chunks, one at a time (cross-warp overlap hides ex2 phases)
#pragma unroll
        for (int j8 = 0; j8 < 8; ++j8) {
            uint32_t Bf[8][2];
            const uint32_t jbase = tbase + (uint32_t)(j8 * 8 * 256);
#pragma unroll
            for (int kk = 0; kk < 4; ++kk)
                ldsm_x4(Bf[2 * kk][0], Bf[2 * kk][1],
                        Bf[2 * kk + 1][0], Bf[2 * kk + 1][1],
                        jbase + colsw[kk]);
            float C0[4] = {0.f, 0.f, 0.f, 0.f};
            float C1[4] = {0.f, 0.f, 0.f, 0.f};
#pragma unroll
            for (int ks = 0; ks < 8; ++ks) {
                mma_bf16(C0, Afrag[0][ks], Bf[ks]);
                mma_bf16(C1, Afrag[1][ks], Bf[ks]);
            }
            su[0][0] += ex2(C0[0]) + ex2(C0[1]);
            su[0][1] += ex2(C0[2]) + ex2(C0[3]);
            su[1][0] += ex2(C1[0]) + ex2(C1[1]);
            su[1][1] += ex2(C1[2]) + ex2(C1[3]);
        }
        __syncthreads();
        if (t + 2 < len) { loadB(t + 2); CP_COMMIT(); }
    }

    // ---- deterministic reduction ----
#pragma unroll
    for (int ms = 0; ms < 2; ++ms)
#pragma unroll
        for (int h = 0; h < 2; ++h) {
            float x = su[ms][h];
            x += __shfl_xor_sync(0xffffffffu, x, 1);
            x += __shfl_xor_sync(0xffffffffu, x, 2);
            su[ms][h] = x;
        }
    __syncthreads();
    float* sred = (float*)smem;
    if ((lane & 3) == 0) {
#pragma unroll
        for (int ms = 0; ms < 2; ++ms)
#pragma unroll
            for (int h = 0; h < 2; ++h) {
                int srow = warp_m * 32 + ms * 16 + h * 8 + (lane >> 2);
                sred[warp_n * 128 + srow] = su[ms][h];
            }
    }
    __syncthreads();
    if (tid < 128) {
        int u = mtile * NSEG + seg;
        d_partialU[u * 128 + tid] = sred[tid] + sred[128 + tid];
    }

    // ---- signal arrival (release) ----
    __threadfence();
    __syncthreads();
    if (tid == 0) atomicAdd(&d_arrive, 1u);
}

// ---------------- launch ----------------
extern "C" void kernel_launch(void* const* d_in, const int* in_sizes, int n_in,
                              void* d_out, int out_size) {
    const void*  toks = d_in[0];
    const float* emb  = (const float*)d_in[1];
    const float* Wm   = (const float*)d_in[2];
    float* out = (float*)d_out;

    cudaFuncSetAttribute(gemm_sumexp_kernel,
                         cudaFuncAttributeMaxDynamicSharedMemorySize, SMEM_MAIN);

    prep_kernel<<<NCPAD + (VOCAB * DIM / 8 + 127) / 128, 128>>>(toks, emb, Wm);
    gemm_sumexp_kernel<<<NUNITS + 1, 256, SMEM_MAIN>>>(out);
}

// round 14
// speedup vs baseline: 1.7829x; 1.0139x over previous
#include <cuda_runtime.h>
#include <cuda_bf16.h>
#include <math.h>
#include <stdint.h>

// ---------------- problem constants ----------------
#define LSEQ   4096
#define WIN    5
#define NC     4086
#define NCPAD  4096
#define VOCAB  32000
#define DIM    128
#define MT     32              // m-tiles (128 centers each)
#define NSEG   9               // n-segments (7x28 + 2x27 = 250 tiles)
#define NUNITS (MT * NSEG)     // 288 CTAs (one wave at 2 CTAs/SM)
#define LOG2E  1.4426950408889634f

// prep grid: 2048 ctx blocks (2 centers each) + 1000 wconv blocks (256 thr)
#define CTXB   (NCPAD / 2)                 // 2048
#define WCB    ((VOCAB * DIM / 8) / 256)   // 2000 uint4-elems/block? -> 512000/256 = 2000... careful

// ---------------- device scratch ----------------
__device__ __nv_bfloat16  d_ctxh[NCPAD * DIM];   // bf16(ctx * log2e)
__device__ __nv_bfloat16  d_Wh[VOCAB * DIM];     // bf16(W)
__device__ float          d_tgtlogit[NCPAD];
__device__ float          d_partialU[NUNITS * 128];
__device__ float          d_blocksum[32];
__device__ unsigned       d_arrive;              // zero-init; self-resetting

// ---------------- asm helpers ----------------
__device__ __forceinline__ uint32_t smem_to_u32(const void* p) {
    uint32_t a;
    asm("{ .reg .u64 t; cvta.to.shared.u64 t, %1; cvt.u32.u64 %0, t; }" : "=r"(a) : "l"(p));
    return a;
}
#define CP_ASYNC16(dst, src) \
    asm volatile("cp.async.cg.shared.global [%0], [%1], 16;" :: "r"(dst), "l"(src))
#define CP_COMMIT() asm volatile("cp.async.commit_group;" ::: "memory")
#define CP_WAIT1()  asm volatile("cp.async.wait_group 1;" ::: "memory")

__device__ __forceinline__ void ldsm_x4(uint32_t& r0, uint32_t& r1, uint32_t& r2,
                                        uint32_t& r3, uint32_t addr) {
    asm volatile("ldmatrix.sync.aligned.m8n8.x4.shared.b16 {%0,%1,%2,%3}, [%4];"
                 : "=r"(r0), "=r"(r1), "=r"(r2), "=r"(r3) : "r"(addr));
}
__device__ __forceinline__ void mma_bf16(float* c, const uint32_t* a, const uint32_t* b) {
    asm volatile("mma.sync.aligned.m16n8k16.row.col.f32.bf16.bf16.f32 "
                 "{%0,%1,%2,%3}, {%4,%5,%6,%7}, {%8,%9}, {%0,%1,%2,%3};"
                 : "+f"(c[0]), "+f"(c[1]), "+f"(c[2]), "+f"(c[3])
                 : "r"(a[0]), "r"(a[1]), "r"(a[2]), "r"(a[3]), "r"(b[0]), "r"(b[1]));
}
__device__ __forceinline__ float ex2(float x) {
    float y;
    asm("ex2.approx.f32 %0, %1;" : "=f"(y) : "f"(x));
    return y;
}

// ---------------- prep kernel ----------------
// blocks [0, CTXB): 2 centers each (256 threads)
// blocks [CTXB, ...): W -> bf16 (256 threads, 1 uint4/thread)
__global__ void prep_kernel(const void* __restrict__ toks,
                            const float* __restrict__ emb,
                            const float* __restrict__ Wm) {
    if (blockIdx.x < CTXB) {
        __shared__ int   s_is64;
        __shared__ int   stok[13];
        __shared__ float sred[8];
        const int tid  = threadIdx.x;
        const int half = tid >> 7;              // 0 or 1: which center
        const int d    = tid & 127;
        const int c    = blockIdx.x * 2 + half;
        const int* p32 = (const int*)toks;
        if (tid == 0) {
            int any = 0;
#pragma unroll
            for (int i = 0; i < 16; ++i) any |= p32[2 * i + 1];
            s_is64 = (any == 0);
        }
        __syncthreads();
        // tokens [base, base+12] cover both centers (center k uses idx k..k+10)
        const int base = blockIdx.x * 2;
        if (tid < 13 && base + tid < LSEQ)
            stok[tid] = s_is64 ? (int)(((const long long*)toks)[base + tid]) : p32[base + tid];
        __syncthreads();
        float s = 0.f;
        if (c < NC) {
#pragma unroll
            for (int j = 0; j < 11; ++j) {
                if (j == WIN) continue;
                s += emb[(size_t)stok[half + j] * DIM + d];
            }
            s *= (1.0f / (2 * WIN));
        }
        d_ctxh[c * DIM + d] = __float2bfloat16(s * LOG2E);
        if (c < NC) {
            float pr = s * Wm[(size_t)stok[half + WIN] * DIM + d];
#pragma unroll
            for (int o = 16; o; o >>= 1) pr += __shfl_xor_sync(0xffffffffu, pr, o);
            if ((tid & 31) == 0) sred[tid >> 5] = pr;
        }
        __syncthreads();
        if (d == 0 && c < NC) {
            int b4 = half * 4;
            d_tgtlogit[c] = sred[b4] + sred[b4 + 1] + sred[b4 + 2] + sred[b4 + 3];
        }
    } else {
        int i = (blockIdx.x - CTXB) * 256 + threadIdx.x;  // uint4 index
        if (i >= VOCAB * DIM / 8) return;
        float4 w0 = ((const float4*)Wm)[2 * i];
        float4 w1 = ((const float4*)Wm)[2 * i + 1];
        uint4 v;
        v.x = ((uint32_t)__bfloat16_as_ushort(__float2bfloat16(w0.y)) << 16) | __bfloat16_as_ushort(__float2bfloat16(w0.x));
        v.y = ((uint32_t)__bfloat16_as_ushort(__float2bfloat16(w0.w)) << 16) | __bfloat16_as_ushort(__float2bfloat16(w0.z));
        v.z = ((uint32_t)__bfloat16_as_ushort(__float2bfloat16(w1.y)) << 16) | __bfloat16_as_ushort(__float2bfloat16(w1.x));
        v.w = ((uint32_t)__bfloat16_as_ushort(__float2bfloat16(w1.w)) << 16) | __bfloat16_as_ushort(__float2bfloat16(w1.z));
        ((uint4*)d_Wh)[i] = v;
    }
}

// ---------------- main fused GEMM + sum-exp (R11 exact form) ----------------
// 2 CTAs/SM: smem per CTA = A 32KB + 2-stage B 64KB = 96KB; regs <= 128.
#define SMEM_A_OFF 0
#define SMEM_B_OFF 32768
#define SMEM_MAIN  (32768 + 2 * 32768)

__global__ void __launch_bounds__(256, 2) gemm_sumexp_kernel() {
    extern __shared__ char smem[];
    uint32_t sb = smem_to_u32(smem);
    const int tid  = threadIdx.x;
    const int lane = tid & 31;
    const int wid  = tid >> 5;
    const int warp_m = wid & 3;
    const int warp_n = wid >> 2;
    const int mtile = blockIdx.x;
    const int seg   = blockIdx.y;
    const int nbase = (seg < 7) ? seg * 28 : 196 + (seg - 7) * 27;
    const int len   = (seg < 7) ? 28 : 27;

    const uint32_t sA = sb + SMEM_A_OFF;
    const uint32_t sB = sb + SMEM_B_OFF;

    // ---- async-load A tile (128x128 bf16, swizzled) ----
    {
        const char* src = (const char*)(d_ctxh + (size_t)mtile * 128 * DIM);
#pragma unroll
        for (int i = 0; i < 8; ++i) {
            int j = tid + i * 256;
            int row = j >> 4, cb = j & 15;
            CP_ASYNC16(sA + row * 256 + ((cb ^ (row & 7)) << 4),
                       src + row * 256 + cb * 16);
        }
    }
    auto loadB = [&](int t) {
        const char* src = (const char*)(d_Wh + (size_t)(nbase + t) * 128 * DIM);
        uint32_t dstb = sB + (t & 1) * 32768;
#pragma unroll
        for (int i = 0; i < 8; ++i) {
            int j = tid + i * 256;
            int row = j >> 4, cb = j & 15;
            CP_ASYNC16(dstb + row * 256 + ((cb ^ (row & 7)) << 4),
                       src + row * 256 + cb * 16);
        }
    };
    loadB(0); CP_COMMIT();   // group: A + B0
    loadB(1); CP_COMMIT();

    // B ldsm addressing: row&7 == lane&7 for all chunks
    const uint32_t rowbase = (uint32_t)(warp_n * 64 + (lane & 7)) * 256;
    uint32_t colsw[4];
#pragma unroll
    for (int kk = 0; kk < 4; ++kk)
        colsw[kk] = (uint32_t)(((kk * 4 + (lane >> 3)) ^ (lane & 7)) << 4);

    uint32_t Afrag[2][8][4];          // persistent A fragments (64 regs)
    float    su[2][2] = {{0.f, 0.f}, {0.f, 0.f}};

    for (int t = 0; t < len; ++t) {
        CP_WAIT1();
        __syncthreads();
        if (t == 0) {
#pragma unroll
            for (int ms = 0; ms < 2; ++ms)
#pragma unroll
                for (int ks = 0; ks < 8; ++ks) {
                    int row = warp_m * 32 + ms * 16 + (lane & 7) + 8 * ((lane >> 3) & 1);
                    int cb  = ks * 2 + (lane >> 4);
                    uint32_t addr = sA + row * 256 + ((cb ^ (row & 7)) << 4);
                    ldsm_x4(Afrag[ms][ks][0], Afrag[ms][ks][1],
                            Afrag[ms][ks][2], Afrag[ms][ks][3], addr);
                }
        }
        const uint32_t tbase = sB + (t & 1) * 32768 + rowbase;

        // 8 n8-chunks, one at a time (cross-warp overlap hides ex2 phases)
#pragma unroll
        for (int j8 = 0; j8 < 8; ++j8) {
            uint32_t Bf[8][2];
            const uint32_t jbase = tbase + (uint32_t)(j8 * 8 * 256);
#pragma unroll
            for (int kk = 0; kk < 4; ++kk)
                ldsm_x4(Bf[2 * kk][0], Bf[2 * kk][1],
                        Bf[2 * kk + 1][0], Bf[2 * kk + 1][1],
                        jbase + colsw[kk]);
            float C0[4] = {0.f, 0.f, 0.f, 0.f};
            float C1[4] = {0.f, 0.f, 0.f, 0.f};
#pragma unroll
            for (int ks = 0; ks < 8; ++ks) {
                mma_bf16(C0, Afrag[0][ks], Bf[ks]);
                mma_bf16(C1, Afrag[1][ks], Bf[ks]);
            }
            su[0][0] += ex2(C0[0]) + ex2(C0[1]);
            su[0][1] += ex2(C0[2]) + ex2(C0[3]);
            su[1][0] += ex2(C1[0]) + ex2(C1[1]);
            su[1][1] += ex2(C1[2]) + ex2(C1[3]);
        }
        __syncthreads();
        if (t + 2 < len) { loadB(t + 2); CP_COMMIT(); }
    }

    // ---- deterministic reduction ----
#pragma unroll
    for (int ms = 0; ms < 2; ++ms)
#pragma unroll
        for (int h = 0; h < 2; ++h) {
            float x = su[ms][h];
            x += __shfl_xor_sync(0xffffffffu, x, 1);
            x += __shfl_xor_sync(0xffffffffu, x, 2);
            su[ms][h] = x;
        }
    __syncthreads();
    float* sred = (float*)smem;
    if ((lane & 3) == 0) {
#pragma unroll
        for (int ms = 0; ms < 2; ++ms)
#pragma unroll
            for (int h = 0; h < 2; ++h) {
                int srow = warp_m * 32 + ms * 16 + h * 8 + (lane >> 2);
                sred[warp_n * 128 + srow] = su[ms][h];
            }
    }
    __syncthreads();
    if (tid < 128) {
        int u = mtile * NSEG + seg;
        d_partialU[u * 128 + tid] = sred[tid] + sred[128 + tid];
    }
}

// ---------------- loss: single launch, last-block finishes ----------------
__global__ void loss_kernel(float* __restrict__ out) {
    __shared__ float sred[4];
    __shared__ int   slast;
    int m = blockIdx.x, r = threadIdx.x;
    int c = m * 128 + r;
    float s = 0.f;
    if (c < NC) {
        float t = 0.f;
#pragma unroll
        for (int g = 0; g < NSEG; ++g) t += d_partialU[(m * NSEG + g) * 128 + r];
        s = __logf(t) - d_tgtlogit[c];
    }
#pragma unroll
    for (int o = 16; o; o >>= 1) s += __shfl_xor_sync(0xffffffffu, s, o);
    if ((r & 31) == 0) sred[r >> 5] = s;
    __syncthreads();
    if (r == 0) {
        d_blocksum[m] = sred[0] + sred[1] + sred[2] + sred[3];
        __threadfence();
        slast = (atomicAdd(&d_arrive, 1u) == 31u);
    }
    __syncthreads();
    if (slast && r == 0) {
        float tot = 0.f;
#pragma unroll
        for (int i = 0; i < 32; ++i) tot += __ldcg(&d_blocksum[i]);
        out[0] = tot;
        d_arrive = 0u;
    }
}

// ---------------- launch ----------------
extern "C" void kernel_launch(void* const* d_in, const int* in_sizes, int n_in,
                              void* d_out, int out_size) {
    const void*  toks = d_in[0];
    const float* emb  = (const float*)d_in[1];
    const float* Wm   = (const float*)d_in[2];
    float* out = (float*)d_out;

    cudaFuncSetAttribute(gemm_sumexp_kernel,
                         cudaFuncAttributeMaxDynamicSharedMemorySize, SMEM_MAIN);

    int wconv_blocks = (VOCAB * DIM / 8 + 255) / 256;   // 2000
    prep_kernel<<<CTXB + wconv_blocks, 256>>>(toks, emb, Wm);
    gemm_sumexp_kernel<<<dim3(MT, NSEG), 256, SMEM_MAIN>>>();
    loss_kernel<<<32, 128>>>(out);
}